// round 10
// baseline (speedup 1.0000x reference)
#include <cuda_runtime.h>
#include <cstdint>
#include <math.h>

// poses: (4096, 3, 128, 17) float32, channel 1 used.
// out:   [ma(7,4096); mi(7,4096)] stored as float32.
//
// One warp per batch. Channel-1 slice (2176 floats, 8704 B, 16B-aligned) is
// staged to smem with cp.async in TWO commit groups:
//   group A: chunks i=0..8   (floats 0..1151)  -> covers frames 0..63
//   group B: chunks i=9..16  (floats 1152..2175)
// Lane L's frames are L, L+32 (group A data) and L+64, L+96 (needs B).
// We wait_group 1 (A done), compute frames 0-1 while B is in flight, then
// wait_group 0 and compute frames 2-3.

#define NB 4096
#define FRAMES 128
#define JOINTS 17
#define ROW_F (FRAMES * JOINTS)   // 2176
#define WPB 8                     // warps per block = batches per block

__device__ __forceinline__ int f2o(float f) {
    int b = __float_as_int(f);
    return b ^ ((b >> 31) & 0x7fffffff);
}
__device__ __forceinline__ float o2f(int k) {
    return __int_as_float(k ^ ((k >> 31) & 0x7fffffff));
}
__device__ __forceinline__ float warp_max_f32(float v) {
    return o2f(__reduce_max_sync(0xffffffffu, f2o(v)));
}
__device__ __forceinline__ float warp_min_f32(float v) {
    return o2f(__reduce_min_sync(0xffffffffu, f2o(v)));
}

// Process two frames (rows fa, fb of this warp's smem slice), accumulate into r[14].
__device__ __forceinline__ void do_frame(const float* __restrict__ row, float* __restrict__ r)
{
    float x[JOINTS];
    #pragma unroll
    for (int j = 0; j < JOINTS; j++) x[j] = row[j];

    const float x0 = x[0];
    const float ratio = __fmul_rn(__fadd_rn(__fsub_rn(x[5], x0), __fsub_rn(x[6], x0)), 0.5f);
    const float rcp = __frcp_rn(ratio);

    float v[JOINTS];
    v[0] = 0.0f;                               // (x0-x0)/ratio == 0 exactly
    #pragma unroll
    for (int j = 1; j < JOINTS; j++)
        v[j] = __fmul_rn(__fsub_rn(x[j], x0), rcp);

    float pmax[7], pmin[7];
    #pragma unroll
    for (int p = 0; p < 7; p++) { pmax[p] = -INFINITY; pmin[p] = INFINITY; }
    #pragma unroll
    for (int j = 0; j < JOINTS; j++) {
        const int p = (j < 5) ? 0 : ((j - 3) >> 1);
        pmax[p] = fmaxf(pmax[p], v[j]);
        pmin[p] = fminf(pmin[p], v[j]);
    }
    float fm = pmin[0];
    #pragma unroll
    for (int p = 1; p < 7; p++) fm = fminf(fm, pmin[p]);
    // max/min commute with the monotone RN-subtraction of fm -> matches reference
    #pragma unroll
    for (int p = 0; p < 7; p++) {
        r[p]     = fmaxf(r[p],     __fsub_rn(pmax[p], fm));
        r[p + 7] = fminf(r[p + 7], __fsub_rn(pmin[p], fm));
    }
}

__global__ __launch_bounds__(32 * WPB) void divid_part_kernel(
    const float* __restrict__ poses, float* __restrict__ out)
{
    __shared__ __align__(16) float s[WPB][ROW_F];

    const int lane = threadIdx.x & 31;
    const int w    = threadIdx.x >> 5;
    const int b    = blockIdx.x * WPB + w;

    const float4* g4 = reinterpret_cast<const float4*>(poses + ((size_t)b * 3 + 1) * ROW_F);
    unsigned int sbase;
    asm("{ .reg .u64 t; cvta.to.shared.u64 t, %1; cvt.u32.u64 %0, t; }"
        : "=r"(sbase) : "l"(&s[w][0]));

    // Group A: chunks 0..8 (floats 0..1151 >= frames 0..63's floats 0..1087)
    #pragma unroll
    for (int i = 0; i < 9; i++) {
        const int idx = lane + i * 32;
        asm volatile("cp.async.cg.shared.global [%0], [%1], 16;"
                     :: "r"(sbase + idx * 16), "l"(g4 + idx));
    }
    asm volatile("cp.async.commit_group;");
    // Group B: chunks 9..16
    #pragma unroll
    for (int i = 9; i < 17; i++) {
        const int idx = lane + i * 32;
        asm volatile("cp.async.cg.shared.global [%0], [%1], 16;"
                     :: "r"(sbase + idx * 16), "l"(g4 + idx));
    }
    asm volatile("cp.async.commit_group;");

    float r[14];
    #pragma unroll
    for (int k = 0; k < 7; k++) { r[k] = -INFINITY; r[k + 7] = INFINITY; }

    // Wait for group A only; frames lane, lane+32 are ready.
    asm volatile("cp.async.wait_group 1;");
    __syncwarp();
    do_frame(&s[w][lane * JOINTS], r);
    do_frame(&s[w][(lane + 32) * JOINTS], r);

    // Wait for the rest; frames lane+64, lane+96.
    asm volatile("cp.async.wait_group 0;");
    __syncwarp();
    do_frame(&s[w][(lane + 64) * JOINTS], r);
    do_frame(&s[w][(lane + 96) * JOINTS], r);

    // ---- Warp reduction: 14 integer REDUX ops (broadcast to all lanes).
    #pragma unroll
    for (int k = 0; k < 7; k++) {
        r[k]     = warp_max_f32(r[k]);
        r[k + 7] = warp_min_f32(r[k + 7]);
    }

    float bottom = r[0], top = r[7];
    #pragma unroll
    for (int p = 1; p < 7; p++) {
        bottom = fmaxf(bottom, r[p]);
        top    = fminf(top,    r[p + 7]);
    }
    const float denom = __fsub_rn(bottom, top);

    // ---- Epilogue (exact IEEE divides, 14 total): all lanes compute, lane 0 stores.
    int ma_[7], mi_[7];
    #pragma unroll
    for (int p = 0; p < 7; p++) {
        int ma = (int)ceilf (__fmul_rn(__fdiv_rn(__fsub_rn(r[p],     top), denom), 64.0f));
        int mi = (int)floorf(__fmul_rn(__fdiv_rn(__fsub_rn(r[p + 7], top), denom), 64.0f));
        const int hi = (p + 1) * 9, lo = p * 9;
        if (ma <= mi || ma - mi > 30) { ma = hi; mi = lo; }
        ma_[p] = ma; mi_[p] = mi;
    }
    if (lane == 0) {
        #pragma unroll
        for (int p = 0; p < 7; p++) {
            out[p * NB + b]       = (float)ma_[p];
            out[(7 + p) * NB + b] = (float)mi_[p];
        }
    }
}

extern "C" void kernel_launch(void* const* d_in, const int* in_sizes, int n_in,
                              void* d_out, int out_size)
{
    const float* poses = (const float*)d_in[0];
    float* out = (float*)d_out;
    divid_part_kernel<<<NB / WPB, 32 * WPB>>>(poses, out);
}

// round 11
// speedup vs baseline: 1.1189x; 1.1189x over previous
#include <cuda_runtime.h>
#include <cstdint>
#include <math.h>

// poses: (4096, 3, 128, 17) float32, channel 1 used.
// out:   [ma(7,4096); mi(7,4096)] stored as float32.
//
// One warp per batch, pipelined: each warp handles NPW consecutive batches with
// double-buffered smem. The cp.async group for batch k+1 is issued BEFORE the
// wait on batch k's group, so batch k+1's DRAM latency hides behind batch k's
// compute. Only the prologue load is exposed.

#define NB 4096
#define FRAMES 128
#define JOINTS 17
#define ROW_F (FRAMES * JOINTS)   // 2176 floats; 8704 B slice, 16B-aligned
#define WPB 4                     // warps per block
#define NPW 4                     // batches per warp

__device__ __forceinline__ int f2o(float f) {
    int b = __float_as_int(f);
    return b ^ ((b >> 31) & 0x7fffffff);
}
__device__ __forceinline__ float o2f(int k) {
    return __int_as_float(k ^ ((k >> 31) & 0x7fffffff));
}
__device__ __forceinline__ float warp_max_f32(float v) {
    return o2f(__reduce_max_sync(0xffffffffu, f2o(v)));
}
__device__ __forceinline__ float warp_min_f32(float v) {
    return o2f(__reduce_min_sync(0xffffffffu, f2o(v)));
}

__device__ __forceinline__ void issue_batch(const float* __restrict__ poses,
                                            unsigned int sdst, int b, int lane)
{
    const float4* g4 = reinterpret_cast<const float4*>(poses + ((size_t)b * 3 + 1) * ROW_F);
    #pragma unroll
    for (int i = 0; i < 17; i++) {
        const int idx = lane + i * 32;
        asm volatile("cp.async.cg.shared.global [%0], [%1], 16;"
                     :: "r"(sdst + idx * 16), "l"(g4 + idx));
    }
    asm volatile("cp.async.commit_group;");
}

__device__ __forceinline__ void do_frame(const float* __restrict__ row, float* __restrict__ r)
{
    float x[JOINTS];
    #pragma unroll
    for (int j = 0; j < JOINTS; j++) x[j] = row[j];

    const float x0 = x[0];
    const float ratio = __fmul_rn(__fadd_rn(__fsub_rn(x[5], x0), __fsub_rn(x[6], x0)), 0.5f);
    const float rcp = __frcp_rn(ratio);

    float v[JOINTS];
    v[0] = 0.0f;                               // (x0-x0)/ratio == 0 exactly
    #pragma unroll
    for (int j = 1; j < JOINTS; j++)
        v[j] = __fmul_rn(__fsub_rn(x[j], x0), rcp);

    float pmax[7], pmin[7];
    #pragma unroll
    for (int p = 0; p < 7; p++) { pmax[p] = -INFINITY; pmin[p] = INFINITY; }
    #pragma unroll
    for (int j = 0; j < JOINTS; j++) {
        const int p = (j < 5) ? 0 : ((j - 3) >> 1);
        pmax[p] = fmaxf(pmax[p], v[j]);
        pmin[p] = fminf(pmin[p], v[j]);
    }
    float fm = pmin[0];
    #pragma unroll
    for (int p = 1; p < 7; p++) fm = fminf(fm, pmin[p]);
    // max/min commute with the monotone RN-subtraction of fm -> matches reference
    #pragma unroll
    for (int p = 0; p < 7; p++) {
        r[p]     = fmaxf(r[p],     __fsub_rn(pmax[p], fm));
        r[p + 7] = fminf(r[p + 7], __fsub_rn(pmin[p], fm));
    }
}

__global__ __launch_bounds__(32 * WPB) void divid_part_kernel(
    const float* __restrict__ poses, float* __restrict__ out)
{
    __shared__ __align__(16) float s[WPB][2][ROW_F];

    const int lane = threadIdx.x & 31;
    const int w    = threadIdx.x >> 5;
    const int b0   = (blockIdx.x * WPB + w) * NPW;

    unsigned int sbuf[2];
    asm("{ .reg .u64 t; cvta.to.shared.u64 t, %1; cvt.u32.u64 %0, t; }"
        : "=r"(sbuf[0]) : "l"(&s[w][0][0]));
    asm("{ .reg .u64 t; cvta.to.shared.u64 t, %1; cvt.u32.u64 %0, t; }"
        : "=r"(sbuf[1]) : "l"(&s[w][1][0]));

    // Prologue: load batch 0.
    issue_batch(poses, sbuf[0], b0, lane);

    #pragma unroll
    for (int k = 0; k < NPW; k++) {
        // Prefetch next batch into the other buffer, then wait for current.
        if (k + 1 < NPW) {
            issue_batch(poses, sbuf[(k + 1) & 1], b0 + k + 1, lane);
            asm volatile("cp.async.wait_group 1;");
        } else {
            asm volatile("cp.async.wait_group 0;");
        }
        __syncwarp();

        const float* sw = &s[w][k & 1][0];
        const int b = b0 + k;

        float r[14];
        #pragma unroll
        for (int q = 0; q < 7; q++) { r[q] = -INFINITY; r[q + 7] = INFINITY; }

        do_frame(sw + (size_t)lane * JOINTS,        r);
        do_frame(sw + (size_t)(lane + 32) * JOINTS, r);
        do_frame(sw + (size_t)(lane + 64) * JOINTS, r);
        do_frame(sw + (size_t)(lane + 96) * JOINTS, r);

        // Warp reduction: 14 integer REDUX ops (broadcast to all lanes).
        #pragma unroll
        for (int q = 0; q < 7; q++) {
            r[q]     = warp_max_f32(r[q]);
            r[q + 7] = warp_min_f32(r[q + 7]);
        }

        float bottom = r[0], top = r[7];
        #pragma unroll
        for (int p = 1; p < 7; p++) {
            bottom = fmaxf(bottom, r[p]);
            top    = fminf(top,    r[p + 7]);
        }
        const float denom = __fsub_rn(bottom, top);

        int ma_[7], mi_[7];
        #pragma unroll
        for (int p = 0; p < 7; p++) {
            int ma = (int)ceilf (__fmul_rn(__fdiv_rn(__fsub_rn(r[p],     top), denom), 64.0f));
            int mi = (int)floorf(__fmul_rn(__fdiv_rn(__fsub_rn(r[p + 7], top), denom), 64.0f));
            const int hi = (p + 1) * 9, lo = p * 9;
            if (ma <= mi || ma - mi > 30) { ma = hi; mi = lo; }
            ma_[p] = ma; mi_[p] = mi;
        }
        if (lane == 0) {
            #pragma unroll
            for (int p = 0; p < 7; p++) {
                out[p * NB + b]       = (float)ma_[p];
                out[(7 + p) * NB + b] = (float)mi_[p];
            }
        }
        // Ensure all lanes finished reading this buffer before it is reused
        // (next reuse is 2 iterations away; the wait+syncwarp above also orders,
        // but keep the warp converged here).
        __syncwarp();
    }
}

extern "C" void kernel_launch(void* const* d_in, const int* in_sizes, int n_in,
                              void* d_out, int out_size)
{
    const float* poses = (const float*)d_in[0];
    float* out = (float*)d_out;
    divid_part_kernel<<<NB / (WPB * NPW), 32 * WPB>>>(poses, out);
}

// round 12
// speedup vs baseline: 1.3208x; 1.1805x over previous
#include <cuda_runtime.h>
#include <cstdint>
#include <math.h>

// poses: (4096, 3, 128, 17) float32, channel 1 used.
// out:   [ma(7,4096); mi(7,4096)] stored as float32.
//
// One 64-thread block (2 warps) per batch, grid 4096.
// Thread t handles frames t and t+64. smem = 8.8 KB/block -> ~25 blocks/SM
// = ~50 resident warps/SM (2.5x R8), with half the per-thread work.

#define NB 4096
#define FRAMES 128
#define JOINTS 17
#define ROW_F (FRAMES * JOINTS)   // 2176 floats; 8704 B slice, 16B-aligned
#define NCHUNK (ROW_F / 4)        // 544 float4 chunks

__device__ __forceinline__ int f2o(float f) {
    int b = __float_as_int(f);
    return b ^ ((b >> 31) & 0x7fffffff);
}
__device__ __forceinline__ float o2f(int k) {
    return __int_as_float(k ^ ((k >> 31) & 0x7fffffff));
}
__device__ __forceinline__ float warp_max_f32(float v) {
    return o2f(__reduce_max_sync(0xffffffffu, f2o(v)));
}
__device__ __forceinline__ float warp_min_f32(float v) {
    return o2f(__reduce_min_sync(0xffffffffu, f2o(v)));
}

__device__ __forceinline__ void do_frame(const float* __restrict__ row, float* __restrict__ r)
{
    float x[JOINTS];
    #pragma unroll
    for (int j = 0; j < JOINTS; j++) x[j] = row[j];

    const float x0 = x[0];
    const float ratio = __fmul_rn(__fadd_rn(__fsub_rn(x[5], x0), __fsub_rn(x[6], x0)), 0.5f);
    const float rcp = __frcp_rn(ratio);

    float v[JOINTS];
    v[0] = 0.0f;                               // (x0-x0)/ratio == 0 exactly
    #pragma unroll
    for (int j = 1; j < JOINTS; j++)
        v[j] = __fmul_rn(__fsub_rn(x[j], x0), rcp);

    float pmax[7], pmin[7];
    #pragma unroll
    for (int p = 0; p < 7; p++) { pmax[p] = -INFINITY; pmin[p] = INFINITY; }
    #pragma unroll
    for (int j = 0; j < JOINTS; j++) {
        const int p = (j < 5) ? 0 : ((j - 3) >> 1);
        pmax[p] = fmaxf(pmax[p], v[j]);
        pmin[p] = fminf(pmin[p], v[j]);
    }
    float fm = pmin[0];
    #pragma unroll
    for (int p = 1; p < 7; p++) fm = fminf(fm, pmin[p]);
    // max/min commute with the monotone RN-subtraction of fm -> matches reference
    #pragma unroll
    for (int p = 0; p < 7; p++) {
        r[p]     = fmaxf(r[p],     __fsub_rn(pmax[p], fm));
        r[p + 7] = fminf(r[p + 7], __fsub_rn(pmin[p], fm));
    }
}

__global__ __launch_bounds__(64) void divid_part_kernel(
    const float* __restrict__ poses, float* __restrict__ out)
{
    __shared__ __align__(16) float s[ROW_F];
    __shared__ float red[2][14];

    const int t    = threadIdx.x;      // 0..63
    const int lane = t & 31;
    const int w    = t >> 5;           // warp 0/1
    const int b    = blockIdx.x;

    // ---- Stage channel-1 slice via cp.async: 544 16B chunks over 64 threads.
    const float4* g4 = reinterpret_cast<const float4*>(poses + ((size_t)b * 3 + 1) * ROW_F);
    unsigned int sbase;
    asm("{ .reg .u64 u; cvta.to.shared.u64 u, %1; cvt.u32.u64 %0, u; }"
        : "=r"(sbase) : "l"(&s[0]));
    #pragma unroll
    for (int i = 0; i < 8; i++) {
        const int idx = t + i * 64;
        asm volatile("cp.async.cg.shared.global [%0], [%1], 16;"
                     :: "r"(sbase + idx * 16), "l"(g4 + idx));
    }
    if (t < 32) {                      // chunks 512..543
        const int idx = 512 + t;
        asm volatile("cp.async.cg.shared.global [%0], [%1], 16;"
                     :: "r"(sbase + idx * 16), "l"(g4 + idx));
    }
    asm volatile("cp.async.commit_group;");
    asm volatile("cp.async.wait_group 0;");
    __syncthreads();

    // ---- Two frames per thread: t and t+64 (stride-17 rows, 17 odd -> conflict-free).
    float r[14];
    #pragma unroll
    for (int k = 0; k < 7; k++) { r[k] = -INFINITY; r[k + 7] = INFINITY; }
    do_frame(&s[t * JOINTS], r);
    do_frame(&s[(t + 64) * JOINTS], r);

    // ---- Warp reduction (14 integer REDUX), then cross-warp combine via smem.
    #pragma unroll
    for (int k = 0; k < 7; k++) {
        r[k]     = warp_max_f32(r[k]);
        r[k + 7] = warp_min_f32(r[k + 7]);
    }
    if (lane < 14) red[w][lane] = r[lane];
    __syncthreads();

    #pragma unroll
    for (int k = 0; k < 7; k++) {
        r[k]     = fmaxf(red[0][k],     red[1][k]);
        r[k + 7] = fminf(red[0][k + 7], red[1][k + 7]);
    }

    float bottom = r[0], top = r[7];
    #pragma unroll
    for (int p = 1; p < 7; p++) {
        bottom = fmaxf(bottom, r[p]);
        top    = fminf(top,    r[p + 7]);
    }
    const float denom = __fsub_rn(bottom, top);

    // ---- Epilogue (exact IEEE divides, 14 total): all threads compute, thread 0 stores.
    int ma_[7], mi_[7];
    #pragma unroll
    for (int p = 0; p < 7; p++) {
        int ma = (int)ceilf (__fmul_rn(__fdiv_rn(__fsub_rn(r[p],     top), denom), 64.0f));
        int mi = (int)floorf(__fmul_rn(__fdiv_rn(__fsub_rn(r[p + 7], top), denom), 64.0f));
        const int hi = (p + 1) * 9, lo = p * 9;
        if (ma <= mi || ma - mi > 30) { ma = hi; mi = lo; }
        ma_[p] = ma; mi_[p] = mi;
    }
    if (t == 0) {
        #pragma unroll
        for (int p = 0; p < 7; p++) {
            out[p * NB + b]       = (float)ma_[p];
            out[(7 + p) * NB + b] = (float)mi_[p];
        }
    }
}

extern "C" void kernel_launch(void* const* d_in, const int* in_sizes, int n_in,
                              void* d_out, int out_size)
{
    const float* poses = (const float*)d_in[0];
    float* out = (float*)d_out;
    divid_part_kernel<<<NB, 64>>>(poses, out);
}

// round 13
// speedup vs baseline: 1.8889x; 1.4301x over previous
#include <cuda_runtime.h>
#include <cstdint>
#include <math.h>

// poses: (4096, 3, 128, 17) float32, channel 1 used.
// out:   [ma(7,4096); mi(7,4096)] stored as float32.
//
// R8 structure (best: 11.0 us): 128-thread blocks, one warp per batch,
// coalesced cp.async stage to smem, 4 frames per lane, REDUX reduction.
// This round: arithmetic strength reduction only
//   - rcp.approx.f32 instead of __frcp_rn (1 inst vs ~8)
//   - FMA-fused transform v = fma(x, rcp, -x0*rcp)
//   - epilogue uses ONE divide (inv = 64/denom) instead of 14

#define NB 4096
#define FRAMES 128
#define JOINTS 17
#define ROW_F (FRAMES * JOINTS)   // 2176 floats; 8704 B slice, 16B-aligned
#define WPB 4                     // warps per block = batches per block

__device__ __forceinline__ int f2o(float f) {
    int b = __float_as_int(f);
    return b ^ ((b >> 31) & 0x7fffffff);
}
__device__ __forceinline__ float o2f(int k) {
    return __int_as_float(k ^ ((k >> 31) & 0x7fffffff));
}
__device__ __forceinline__ float warp_max_f32(float v) {
    return o2f(__reduce_max_sync(0xffffffffu, f2o(v)));
}
__device__ __forceinline__ float warp_min_f32(float v) {
    return o2f(__reduce_min_sync(0xffffffffu, f2o(v)));
}
__device__ __forceinline__ float rcp_approx(float x) {
    float r; asm("rcp.approx.f32 %0, %1;" : "=f"(r) : "f"(x)); return r;
}

__device__ __forceinline__ void do_frame(const float* __restrict__ row, float* __restrict__ r)
{
    float x[JOINTS];
    #pragma unroll
    for (int j = 0; j < JOINTS; j++) x[j] = row[j];

    const float x0 = x[0];
    const float ratio = __fmul_rn(__fadd_rn(__fsub_rn(x[5], x0), __fsub_rn(x[6], x0)), 0.5f);
    const float rcp = rcp_approx(ratio);
    const float nb0 = __fmul_rn(-x0, rcp);     // -x0*rcp

    float v[JOINTS];
    v[0] = 0.0f;                               // (x0-x0)/ratio == 0 exactly
    #pragma unroll
    for (int j = 1; j < JOINTS; j++)
        v[j] = __fmaf_rn(x[j], rcp, nb0);      // (x - x0)*rcp, fused

    float pmax[7], pmin[7];
    #pragma unroll
    for (int p = 0; p < 7; p++) { pmax[p] = -INFINITY; pmin[p] = INFINITY; }
    #pragma unroll
    for (int j = 0; j < JOINTS; j++) {
        const int p = (j < 5) ? 0 : ((j - 3) >> 1);
        pmax[p] = fmaxf(pmax[p], v[j]);
        pmin[p] = fminf(pmin[p], v[j]);
    }
    float fm = pmin[0];
    #pragma unroll
    for (int p = 1; p < 7; p++) fm = fminf(fm, pmin[p]);
    // max/min commute with the monotone subtraction of fm
    #pragma unroll
    for (int p = 0; p < 7; p++) {
        r[p]     = fmaxf(r[p],     __fsub_rn(pmax[p], fm));
        r[p + 7] = fminf(r[p + 7], __fsub_rn(pmin[p], fm));
    }
}

__global__ __launch_bounds__(32 * WPB) void divid_part_kernel(
    const float* __restrict__ poses, float* __restrict__ out)
{
    __shared__ __align__(16) float s[WPB][ROW_F];

    const int lane = threadIdx.x & 31;
    const int w    = threadIdx.x >> 5;
    const int b    = blockIdx.x * WPB + w;

    // ---- Stage channel-1 slice into this warp's smem via cp.async (16B chunks).
    const float4* g4 = reinterpret_cast<const float4*>(poses + ((size_t)b * 3 + 1) * ROW_F);
    unsigned int sbase;
    asm("{ .reg .u64 t; cvta.to.shared.u64 t, %1; cvt.u32.u64 %0, t; }"
        : "=r"(sbase) : "l"(&s[w][0]));
    #pragma unroll
    for (int i = 0; i < 17; i++) {
        const int idx = lane + i * 32;
        asm volatile("cp.async.cg.shared.global [%0], [%1], 16;"
                     :: "r"(sbase + idx * 16), "l"(g4 + idx));
    }
    asm volatile("cp.async.commit_group;");
    asm volatile("cp.async.wait_group 0;");
    __syncwarp();

    // ---- 4 frames per lane; stride-17 rows are bank-conflict-free (17 odd).
    float r[14];
    #pragma unroll
    for (int k = 0; k < 7; k++) { r[k] = -INFINITY; r[k + 7] = INFINITY; }
    do_frame(&s[w][lane * JOINTS],        r);
    do_frame(&s[w][(lane + 32) * JOINTS], r);
    do_frame(&s[w][(lane + 64) * JOINTS], r);
    do_frame(&s[w][(lane + 96) * JOINTS], r);

    // ---- Warp reduction: 14 integer REDUX ops (broadcast to all lanes).
    #pragma unroll
    for (int k = 0; k < 7; k++) {
        r[k]     = warp_max_f32(r[k]);
        r[k + 7] = warp_min_f32(r[k + 7]);
    }

    float bottom = r[0], top = r[7];
    #pragma unroll
    for (int p = 1; p < 7; p++) {
        bottom = fmaxf(bottom, r[p]);
        top    = fminf(top,    r[p + 7]);
    }
    // ONE divide for the whole epilogue.
    const float inv = __fdiv_rn(64.0f, __fsub_rn(bottom, top));

    int ma_[7], mi_[7];
    #pragma unroll
    for (int p = 0; p < 7; p++) {
        int ma = (int)ceilf (__fmul_rn(__fsub_rn(r[p],     top), inv));
        int mi = (int)floorf(__fmul_rn(__fsub_rn(r[p + 7], top), inv));
        const int hi = (p + 1) * 9, lo = p * 9;
        if (ma <= mi || ma - mi > 30) { ma = hi; mi = lo; }
        ma_[p] = ma; mi_[p] = mi;
    }
    if (lane == 0) {
        #pragma unroll
        for (int p = 0; p < 7; p++) {
            out[p * NB + b]       = (float)ma_[p];
            out[(7 + p) * NB + b] = (float)mi_[p];
        }
    }
}

extern "C" void kernel_launch(void* const* d_in, const int* in_sizes, int n_in,
                              void* d_out, int out_size)
{
    const float* poses = (const float*)d_in[0];
    float* out = (float*)d_out;
    divid_part_kernel<<<NB / WPB, 32 * WPB>>>(poses, out);
}